// round 4
// baseline (speedup 1.0000x reference)
#include <cuda_runtime.h>

#define BATCH 64
#define NN 512
#define NDIAG 1023
#define NEGV  (-1e30f)
#define INV_LN2 1.44269504088896340736f
#define LN2F    0.69314718055994530942f
#define SENT  0x7fbfffffu   // NaN sentinel: DP values are always finite

// Diagonal-major layout: (k, i) -> k*NN + i, valid i in [max(0,k-511), min(511,k)].
__device__ float g_ddiag[(size_t)BATCH * NDIAG * NN];
__device__ float g_f[(size_t)BATCH * NDIAG * NN];
__device__ float g_b[(size_t)BATCH * NDIAG * NN];
__device__ unsigned int g_maxu;

__device__ __forceinline__ float ex2f(float x) {
    float y; asm("ex2.approx.ftz.f32 %0, %1;" : "=f"(y) : "f"(x)); return y;
}
__device__ __forceinline__ float lg2f(float x) {
    float y; asm("lg2.approx.ftz.f32 %0, %1;" : "=f"(y) : "f"(x)); return y;
}
__device__ __forceinline__ unsigned int fenc(float x) {
    unsigned int b = __float_as_uint(x);
    return (b & 0x80000000u) ? ~b : (b | 0x80000000u);
}
__device__ __forceinline__ float fdec(unsigned int u) {
    return __uint_as_float((u & 0x80000000u) ? (u & 0x7fffffffu) : ~u);
}

__global__ void init_max_kernel() { g_maxu = 0u; }

// ---------------------------------------------------------------------------
// Pre-pass: D (row-major) -> g_ddiag (diag-major), scaled by 1/ln2.
// ---------------------------------------------------------------------------
__global__ void __launch_bounds__(256) diagize_kernel(const float* __restrict__ D) {
    __shared__ float t[32][34];
    int b = blockIdx.z, i0 = blockIdx.y * 32, j0 = blockIdx.x * 32;
    const float* Db = D + (size_t)b * NN * NN;
    float* out = g_ddiag + (size_t)b * NDIAG * NN;
    int tid = threadIdx.x, lane = tid & 31, w = tid >> 5;
#pragma unroll
    for (int r = 0; r < 4; r++) {
        int il = w + 8 * r;
        t[il][lane] = Db[(size_t)(i0 + il) * NN + j0 + lane] * INV_LN2;
    }
    __syncthreads();
#pragma unroll
    for (int r = 0; r < 8; r++) {
        int ld = w + 8 * r;
        if (ld < 63) {
            int ilo = max(0, ld - 31);
            int il = ilo + lane;
            if (il <= min(31, ld)) {
                int k = i0 + j0 + ld;
                out[(size_t)k * NN + (i0 + il)] = t[il][ld - il];
            }
        }
    }
}

__device__ __forceinline__ float lse_cell(float dg, float up, float lf, float dcur) {
    float hi1 = fmaxf(dg, up);
    float lo1 = fminf(dg, up);
    float m   = fmaxf(hi1, lf);
    float o2  = fminf(hi1, lf);
    float s = ex2f(lo1 - m) + ex2f(o2 - m);   // third term is 2^0 = 1
    return dcur + m + lg2f(1.0f + s);
}

// ---------------------------------------------------------------------------
// Barrier-free warp-pipelined wavefront DP.
// 256 threads, thread t owns rows (2t, 2t+1). Warp w owns rows [64w, 64w+64).
// Intra-thread row pair: odd row's up/diag neighbors are in registers.
// Intra-warp: even row's neighbors via __shfl_up of previous-diag values.
// Cross-warp: lane31's odd-row value published per diagonal to edge[w][k];
// consumer lane0 spin-polls against a NaN sentinel (data IS the flag).
// One-directional dependency -> deadlock-free, no __syncthreads in the loop.
// ---------------------------------------------------------------------------
template<bool BWD>
__device__ __forceinline__ void dp_impl(int b, float (*edge)[1024]) {
    const float* dd = g_ddiag + (size_t)b * NDIAG * NN;
    float* out = (BWD ? g_b : g_f) + (size_t)b * NDIAG * NN;
    int tid = threadIdx.x, lane = tid & 31, w = tid >> 5;
    int ia = 2 * tid;                 // even row
    int wbase = 64 * w;               // lane0's even row index
    const int CADDR = 1022 * NN + 511;

    // float2 source: fwd reads {ia, ia+1} ascending; bwd reads mirrored
    // addresses {CADDR-k*NN-ia-1, CADDR-k*NN-ia} -> components swapped.
    long s0  = BWD ? (long)(CADDR - (ia + 1)) : (long)ia;
    long stp = BWD ? -(long)NN : (long)NN;

    float2 pf[8];
#pragma unroll
    for (int q = 0; q < 8; q++) pf[q] = *(const float2*)(dd + s0 + q * stp);

    float va1 = NEGV, va2 = NEGV, vb1 = NEGV, vb2 = NEGV;

    for (int t = 0; t < 128; t++) {
#pragma unroll
        for (int p = 0; p < 8; p++) {
            int k = t * 8 + p;
            float2 dc2 = pf[p];
            {
                int kn = k + 8; if (kn > NDIAG - 1) kn = NDIAG - 1;
                pf[p] = *(const float2*)(dd + s0 + (long)kn * stp);
            }
            if (k <= NDIAG - 1) {
                float dA = BWD ? dc2.y : dc2.x;
                float dB = BWD ? dc2.x : dc2.y;

                float upA = __shfl_up_sync(0xffffffffu, vb1, 1);
                float dgA = __shfl_up_sync(0xffffffffu, vb2, 1);
                if (lane == 0) {
                    if (w == 0) { upA = NEGV; dgA = NEGV; }
                    else if (k >= wbase && k <= wbase + NN - 1) {
                        volatile float* e1 = &edge[w - 1][k - 1];
                        volatile float* e2 = &edge[w - 1][k - 2];
                        float x1, x2;
                        do { x1 = *e1; } while (__float_as_uint(x1) == SENT);
                        do { x2 = *e2; } while (__float_as_uint(x2) == SENT);
                        upA = x1; dgA = x2;
                    }
                }

                int ja = k - ia;
                float vA = NEGV, vB = NEGV;
                if (ja >= 0 && ja < NN) {
                    float dg = (ja == 0) ? ((ia == 0) ? 0.0f : NEGV) : dgA;
                    float lf = (ja == 0) ? NEGV : va1;
                    vA = lse_cell(dg, upA, lf, dA);
                }
                int jb = ja - 1;
                if (jb >= 0 && jb < NN) {
                    float dg = (jb == 0) ? NEGV : va2;   // ib > 0 always
                    float lf = (jb == 0) ? NEGV : vb1;
                    vB = lse_cell(dg, va1, lf, dB);
                }
                if (ja >= 0 && ja <= NN) {   // at least one of the pair valid
                    *(float2*)(out + (size_t)k * NN + ia) = make_float2(vA, vB);
                }
                if (lane == 31) edge[w][k] = vB;   // publish (data = flag)

                va2 = va1; va1 = vA;
                vb2 = vb1; vb1 = vB;
            }
        }
    }
}

__global__ void __launch_bounds__(256) dp_kernel() {
    __shared__ float edge[8][1024];
    int bx = blockIdx.x;
    int b = bx >> 1, dir = bx & 1;
    float* ep = &edge[0][0];
    for (int q = threadIdx.x; q < 8 * 1024; q += 256)
        ep[q] = __uint_as_float(SENT);
    __syncthreads();
    if (dir) dp_impl<true>(b, edge);
    else     dp_impl<false>(b, edge);
}

// ---------------------------------------------------------------------------
// Combine: logit2 = f2 + b2 - d2, de-diagonalize to row-major out,
// per-block max -> encoded atomicMax.
// ---------------------------------------------------------------------------
__global__ void __launch_bounds__(256) combine_kernel(float* __restrict__ out) {
    __shared__ float tile[32][257];
    __shared__ float smax[8];
    int b = blockIdx.y;
    int k0 = blockIdx.x * 32;
    const float* fd = g_f + (size_t)b * NDIAG * NN;
    const float* bd = g_b + (size_t)b * NDIAG * NN;
    const float* dd = g_ddiag + (size_t)b * NDIAG * NN;
    float* ob = out + (size_t)b * NN * NN;
    int tid = threadIdx.x, lane = tid & 31, w = tid >> 5;
    float vmax = -3.4e38f;

    for (int ih = 0; ih < 2; ih++) {
        int ibase = ih * 256;
        for (int kk = 0; kk < 32; kk++) {
            int k = k0 + kk;
            int i = ibase + tid;
            int j = k - i;
            float v = 0.0f;
            if (j >= 0 && j < NN) {
                int a = k * NN + i;
                v = fd[a] + bd[(1022 - k) * NN + (511 - i)] - dd[a];
                vmax = fmaxf(vmax, v);
            }
            tile[kk][tid] = v;
        }
        __syncthreads();
        for (int rr = 0; rr < 32; rr++) {
            int i = ibase + w * 32 + rr;
            int jlo = max(0, k0 - i);
            int jhi = min(NN - 1, k0 + 31 - i);
            int j = jlo + lane;
            if (j <= jhi) {
                int kk = i + j - k0;
                ob[(size_t)i * NN + j] = tile[kk][i - ibase];
            }
        }
        __syncthreads();
    }

#pragma unroll
    for (int o = 16; o > 0; o >>= 1)
        vmax = fmaxf(vmax, __shfl_xor_sync(0xffffffffu, vmax, o));
    if (lane == 0) smax[w] = vmax;
    __syncthreads();
    if (tid == 0) {
        float v = smax[0];
#pragma unroll
        for (int q = 1; q < 8; q++) v = fmaxf(v, smax[q]);
        atomicMax(&g_maxu, fenc(v));
    }
}

__global__ void __launch_bounds__(256) finish_kernel(float* __restrict__ out, int n4) {
    float mx = fdec(g_maxu);
    float4* o4 = (float4*)out;
    int idx = blockIdx.x * blockDim.x + threadIdx.x;
    int stride = gridDim.x * blockDim.x;
    for (int t = idx; t < n4; t += stride) {
        float4 v = o4[t];
        v.x = (v.x - mx) * LN2F;
        v.y = (v.y - mx) * LN2F;
        v.z = (v.z - mx) * LN2F;
        v.w = (v.w - mx) * LN2F;
        o4[t] = v;
    }
}

extern "C" void kernel_launch(void* const* d_in, const int* in_sizes, int n_in,
                              void* d_out, int out_size) {
    const float* d = (const float*)d_in[0];
    float* out = (float*)d_out;

    init_max_kernel<<<1, 1>>>();

    dim3 dgrid(16, 16, BATCH);
    diagize_kernel<<<dgrid, 256>>>(d);

    dp_kernel<<<BATCH * 2, 256>>>();

    dim3 cgrid(32, BATCH);
    combine_kernel<<<cgrid, 256>>>(out);

    finish_kernel<<<4096, 256>>>(out, out_size / 4);
}

// round 5
// speedup vs baseline: 3.2506x; 3.2506x over previous
#include <cuda_runtime.h>

#define BATCH 64
#define NN 512
#define NDIAG 1023
#define NEGV  (-1e30f)
#define INV_LN2 1.44269504088896340736f
#define LN2F    0.69314718055994530942f

// Diagonal-major layout: (k, i) -> k*NN + i, valid i in [max(0,k-511), min(511,k)].
__device__ float g_ddiag[(size_t)BATCH * NDIAG * NN];
__device__ float g_f[(size_t)BATCH * NDIAG * NN];
__device__ float g_b[(size_t)BATCH * NDIAG * NN];
__device__ unsigned int g_maxu;

__device__ __forceinline__ float ex2f(float x) {
    float y; asm("ex2.approx.ftz.f32 %0, %1;" : "=f"(y) : "f"(x)); return y;
}
__device__ __forceinline__ float lg2f(float x) {
    float y; asm("lg2.approx.ftz.f32 %0, %1;" : "=f"(y) : "f"(x)); return y;
}
__device__ __forceinline__ unsigned int fenc(float x) {
    unsigned int b = __float_as_uint(x);
    return (b & 0x80000000u) ? ~b : (b | 0x80000000u);
}
__device__ __forceinline__ float fdec(unsigned int u) {
    return __uint_as_float((u & 0x80000000u) ? (u & 0x7fffffffu) : ~u);
}

__global__ void init_max_kernel() { g_maxu = 0u; }

// ---------------------------------------------------------------------------
// Pre-pass: D (row-major) -> g_ddiag (diag-major), scaled by 1/ln2.
// ---------------------------------------------------------------------------
__global__ void __launch_bounds__(256) diagize_kernel(const float* __restrict__ D) {
    __shared__ float t[32][34];
    int b = blockIdx.z, i0 = blockIdx.y * 32, j0 = blockIdx.x * 32;
    const float* Db = D + (size_t)b * NN * NN;
    float* out = g_ddiag + (size_t)b * NDIAG * NN;
    int tid = threadIdx.x, lane = tid & 31, w = tid >> 5;
#pragma unroll
    for (int r = 0; r < 4; r++) {
        int il = w + 8 * r;
        t[il][lane] = Db[(size_t)(i0 + il) * NN + j0 + lane] * INV_LN2;
    }
    __syncthreads();
#pragma unroll
    for (int r = 0; r < 8; r++) {
        int ld = w + 8 * r;
        if (ld < 63) {
            int ilo = max(0, ld - 31);
            int il = ilo + lane;
            if (il <= min(31, ld)) {
                int k = i0 + j0 + ld;
                out[(size_t)k * NN + (i0 + il)] = t[il][ld - il];
            }
        }
    }
}

__device__ __forceinline__ float lse_cell(float dg, float up, float lf, float dcur) {
    float hi1 = fmaxf(dg, up);
    float lo1 = fminf(dg, up);
    float m   = fmaxf(hi1, lf);
    float o2  = fminf(hi1, lf);
    float s = ex2f(lo1 - m) + ex2f(o2 - m);   // third term is 2^0 = 1
    return dcur + m + lg2f(1.0f + s);
}

// ---------------------------------------------------------------------------
// Wavefront DP: 256 threads, thread t owns rows (2t, 2t+1); warp w owns rows
// [64w, 64w+64). Odd-row neighbors come from registers, even-row neighbors
// from __shfl_up of the previous diagonals' values. The only cross-warp value
// (lane31's odd row) goes through a 4-slot smem ring, ordered by one
// __syncthreads per diagonal (8 warps -> cheap barrier).
// k-loop unrolled x8 keeps the 8-deep float2 LDG prefetch pipeline real.
// ---------------------------------------------------------------------------
template<bool BWD>
__device__ __forceinline__ void dp_impl(int b, float (*edge)[4]) {
    const float* dd = g_ddiag + (size_t)b * NDIAG * NN;
    float* out = (BWD ? g_b : g_f) + (size_t)b * NDIAG * NN;
    int tid = threadIdx.x, lane = tid & 31, w = tid >> 5;
    int ia = 2 * tid;                 // even row
    const int CADDR = 1022 * NN + 511;

    // fwd reads {ia, ia+1}; bwd reads mirrored addresses -> components swapped
    long s0  = BWD ? (long)(CADDR - (ia + 1)) : (long)ia;
    long stp = BWD ? -(long)NN : (long)NN;

    float2 pf[8];
#pragma unroll
    for (int q = 0; q < 8; q++) pf[q] = *(const float2*)(dd + s0 + q * stp);

    float va1 = NEGV, va2 = NEGV, vb1 = NEGV, vb2 = NEGV;

    for (int t = 0; t < 128; t++) {
#pragma unroll
        for (int p = 0; p < 8; p++) {
            int k = t * 8 + p;
            float2 dc2 = pf[p];
            {
                int kn = k + 8; if (kn > NDIAG - 1) kn = NDIAG - 1;
                pf[p] = *(const float2*)(dd + s0 + (long)kn * stp);
            }
            if (k < NDIAG) {                  // uniform over the block
                float dA = BWD ? dc2.y : dc2.x;
                float dB = BWD ? dc2.x : dc2.y;

                float upA = __shfl_up_sync(0xffffffffu, vb1, 1);
                float dgA = __shfl_up_sync(0xffffffffu, vb2, 1);
                if (lane == 0) {
                    if (w == 0) { upA = NEGV; dgA = NEGV; }
                    else {
                        upA = edge[w - 1][(k - 1) & 3];   // diag k-1, row 64w-1
                        dgA = edge[w - 1][(k - 2) & 3];   // diag k-2, row 64w-1
                    }
                }

                int ja = k - ia;
                float vA = NEGV, vB = NEGV;
                if (ja >= 0 && ja < NN) {
                    float dg = (ja == 0) ? ((ia == 0) ? 0.0f : NEGV) : dgA;
                    float lf = (ja == 0) ? NEGV : va1;
                    vA = lse_cell(dg, upA, lf, dA);
                }
                int jb = ja - 1;
                if (jb >= 0 && jb < NN) {
                    float dg = (jb == 0) ? NEGV : va2;   // ib > 0 always
                    float lf = (jb == 0) ? NEGV : vb1;
                    vB = lse_cell(dg, va1, lf, dB);
                }
                if (ja >= 0 && ja <= NN) {
                    *(float2*)(out + (size_t)k * NN + ia) = make_float2(vA, vB);
                }
                if (lane == 31) edge[w][k & 3] = vB;     // publish odd-row value

                va2 = va1; va1 = vA;
                vb2 = vb1; vb1 = vB;
                __syncthreads();               // orders edge write -> next read
            }
        }
    }
}

__global__ void __launch_bounds__(256) dp_kernel() {
    __shared__ float edge[8][4];
    int bx = blockIdx.x;
    int b = bx >> 1, dir = bx & 1;
    if (dir) dp_impl<true>(b, edge);
    else     dp_impl<false>(b, edge);
}

// ---------------------------------------------------------------------------
// Combine: logit2 = f2 + b2 - d2, de-diagonalize to row-major out,
// per-block max -> encoded atomicMax.
// ---------------------------------------------------------------------------
__global__ void __launch_bounds__(256) combine_kernel(float* __restrict__ out) {
    __shared__ float tile[32][257];
    __shared__ float smax[8];
    int b = blockIdx.y;
    int k0 = blockIdx.x * 32;
    const float* fd = g_f + (size_t)b * NDIAG * NN;
    const float* bd = g_b + (size_t)b * NDIAG * NN;
    const float* dd = g_ddiag + (size_t)b * NDIAG * NN;
    float* ob = out + (size_t)b * NN * NN;
    int tid = threadIdx.x, lane = tid & 31, w = tid >> 5;
    float vmax = -3.4e38f;

    for (int ih = 0; ih < 2; ih++) {
        int ibase = ih * 256;
        for (int kk = 0; kk < 32; kk++) {
            int k = k0 + kk;
            int i = ibase + tid;
            int j = k - i;
            float v = 0.0f;
            if (j >= 0 && j < NN) {
                int a = k * NN + i;
                v = fd[a] + bd[(1022 - k) * NN + (511 - i)] - dd[a];
                vmax = fmaxf(vmax, v);
            }
            tile[kk][tid] = v;
        }
        __syncthreads();
        for (int rr = 0; rr < 32; rr++) {
            int i = ibase + w * 32 + rr;
            int jlo = max(0, k0 - i);
            int jhi = min(NN - 1, k0 + 31 - i);
            int j = jlo + lane;
            if (j <= jhi) {
                int kk = i + j - k0;
                ob[(size_t)i * NN + j] = tile[kk][i - ibase];
            }
        }
        __syncthreads();
    }

#pragma unroll
    for (int o = 16; o > 0; o >>= 1)
        vmax = fmaxf(vmax, __shfl_xor_sync(0xffffffffu, vmax, o));
    if (lane == 0) smax[w] = vmax;
    __syncthreads();
    if (tid == 0) {
        float v = smax[0];
#pragma unroll
        for (int q = 1; q < 8; q++) v = fmaxf(v, smax[q]);
        atomicMax(&g_maxu, fenc(v));
    }
}

__global__ void __launch_bounds__(256) finish_kernel(float* __restrict__ out, int n4) {
    float mx = fdec(g_maxu);
    float4* o4 = (float4*)out;
    int idx = blockIdx.x * blockDim.x + threadIdx.x;
    int stride = gridDim.x * blockDim.x;
    for (int t = idx; t < n4; t += stride) {
        float4 v = o4[t];
        v.x = (v.x - mx) * LN2F;
        v.y = (v.y - mx) * LN2F;
        v.z = (v.z - mx) * LN2F;
        v.w = (v.w - mx) * LN2F;
        o4[t] = v;
    }
}

extern "C" void kernel_launch(void* const* d_in, const int* in_sizes, int n_in,
                              void* d_out, int out_size) {
    const float* d = (const float*)d_in[0];
    float* out = (float*)d_out;

    init_max_kernel<<<1, 1>>>();

    dim3 dgrid(16, 16, BATCH);
    diagize_kernel<<<dgrid, 256>>>(d);

    dp_kernel<<<BATCH * 2, 256>>>();

    dim3 cgrid(32, BATCH);
    combine_kernel<<<cgrid, 256>>>(out);

    finish_kernel<<<4096, 256>>>(out, out_size / 4);
}

// round 6
// speedup vs baseline: 3.8090x; 1.1718x over previous
#include <cuda_runtime.h>

#define BATCH 64
#define NN 512
#define NDIAG 1023
#define NEGV  (-1e30f)
#define INV_LN2 1.44269504088896340736f
#define LN2F    0.69314718055994530942f
#define NW 16            // warps per DP CTA
#define DD 8             // diagonals per round
#define NROUNDS (128 + NW - 1)   // 143

// Diagonal-major layout: (k, i) -> k*NN + i, valid i in [max(0,k-511), min(511,k)].
__device__ float g_ddiag[(size_t)BATCH * NDIAG * NN];
__device__ float g_f[(size_t)BATCH * NDIAG * NN];
__device__ float g_b[(size_t)BATCH * NDIAG * NN];
__device__ unsigned int g_maxu;

__device__ __forceinline__ float ex2f(float x) {
    float y; asm("ex2.approx.ftz.f32 %0, %1;" : "=f"(y) : "f"(x)); return y;
}
__device__ __forceinline__ float lg2f(float x) {
    float y; asm("lg2.approx.ftz.f32 %0, %1;" : "=f"(y) : "f"(x)); return y;
}
__device__ __forceinline__ unsigned int fenc(float x) {
    unsigned int b = __float_as_uint(x);
    return (b & 0x80000000u) ? ~b : (b | 0x80000000u);
}
__device__ __forceinline__ float fdec(unsigned int u) {
    return __uint_as_float((u & 0x80000000u) ? (u & 0x7fffffffu) : ~u);
}

__global__ void init_max_kernel() { g_maxu = 0u; }

// ---------------------------------------------------------------------------
// Pre-pass: D (row-major) -> g_ddiag (diag-major), scaled by 1/ln2.
// ---------------------------------------------------------------------------
__global__ void __launch_bounds__(256) diagize_kernel(const float* __restrict__ D) {
    __shared__ float t[32][34];
    int b = blockIdx.z, i0 = blockIdx.y * 32, j0 = blockIdx.x * 32;
    const float* Db = D + (size_t)b * NN * NN;
    float* out = g_ddiag + (size_t)b * NDIAG * NN;
    int tid = threadIdx.x, lane = tid & 31, w = tid >> 5;
#pragma unroll
    for (int r = 0; r < 4; r++) {
        int il = w + 8 * r;
        t[il][lane] = Db[(size_t)(i0 + il) * NN + j0 + lane] * INV_LN2;
    }
    __syncthreads();
#pragma unroll
    for (int r = 0; r < 8; r++) {
        int ld = w + 8 * r;
        if (ld < 63) {
            int ilo = max(0, ld - 31);
            int il = ilo + lane;
            if (il <= min(31, ld)) {
                int k = i0 + j0 + ld;
                out[(size_t)k * NN + (i0 + il)] = t[il][ld - il];
            }
        }
    }
}

__device__ __forceinline__ float lse_cell(float dg, float up, float lf, float dcur) {
    float hi1 = fmaxf(dg, up);
    float lo1 = fminf(dg, up);
    float m   = fmaxf(hi1, lf);
    float o2  = fminf(hi1, lf);
    float s = ex2f(lo1 - m) + ex2f(o2 - m);   // third term is 2^0 = 1
    return dcur + m + lg2f(1.0f + s);
}

// ---------------------------------------------------------------------------
// Skewed-warp wavefront DP. 512 threads, thread = one row, warp w = rows
// [32w, 32w+32). Warp w lags warp w-1 by DD=8 diagonals. Per round a warp
// computes 8 diagonals using intra-warp shfl (1/diag); the 9 cross-warp edge
// values (row 32w-1 at diags kbase-2..kbase+6) are read once per round from
// a 32-slot smem ring written by warp w-1 one round earlier. One
// __syncthreads per round (per 8 diagonals), not per diagonal.
// Ring safety: reader slots (kbase+22..kbase+30 mod 32) never collide with
// same-round writer slots (kbase..kbase+7 mod 32).
// ---------------------------------------------------------------------------
template<bool BWD>
__device__ __forceinline__ void dp_impl(int b, float (*edge)[32]) {
    const float* dd = g_ddiag + (size_t)b * NDIAG * NN;
    float* out = (BWD ? g_b : g_f) + (size_t)b * NDIAG * NN;
    int tid = threadIdx.x, lane = tid & 31, w = tid >> 5;
    int i = tid;                       // my row
    const int CADDR = 1022 * NN + 511; // bwd mirror: addr = CADDR - (k*NN+i)

    float v1 = NEGV, v2 = NEGV;        // my row's values at diag m-1, m-2
    float pf[8];
#pragma unroll
    for (int q = 0; q < 8; q++) {
        int a = q * NN + i;
        pf[q] = dd[BWD ? (CADDR - a) : a];
    }

    for (int r = 0; r < NROUNDS; r++) {
        int kbase = DD * (r - w);
        if (kbase >= 0 && kbase < NDIAG) {
            // edge values from warp above (broadcast LDS, loaded up-front)
            float e[9];
#pragma unroll
            for (int q = 0; q < 9; q++) {
                int kq = kbase - 2 + q;
                e[q] = (w > 0 && kq >= 0 && kq < NDIAG)
                         ? edge[w - 1][kq & 31] : NEGV;
            }
            // prefetch next round's D values
            float npf[8];
#pragma unroll
            for (int q = 0; q < 8; q++) {
                int kn = kbase + 8 + q; if (kn > NDIAG - 1) kn = NDIAG - 1;
                int a = kn * NN + i;
                npf[q] = dd[BWD ? (CADDR - a) : a];
            }

            float sprev = __shfl_up_sync(0xffffffffu, v2, 1); // nbr @ kbase-2
#pragma unroll
            for (int q = 0; q < 8; q++) {
                int k = kbase + q;
                float s1 = __shfl_up_sync(0xffffffffu, v1, 1); // nbr @ k-1
                float up = (lane == 0) ? e[q + 1] : s1;
                float dg = (lane == 0) ? e[q]     : sprev;
                int j = k - i;
                bool valid = (k < NDIAG) && (j >= 0) && (j < NN);
                float dgx = (j == 0) ? ((i == 0) ? 0.0f : NEGV) : dg;
                float lfx = (j == 0) ? NEGV : v1;
                float vnew = lse_cell(dgx, up, lfx, pf[q]);
                vnew = valid ? vnew : NEGV;
                if (valid) out[(size_t)k * NN + i] = vnew;
                if (lane == 31 && k < NDIAG) edge[w][k & 31] = vnew;
                v2 = v1; v1 = vnew; sprev = s1;
            }
#pragma unroll
            for (int q = 0; q < 8; q++) pf[q] = npf[q];
        }
        __syncthreads();   // publishes edge writes to the warp below
    }
}

__global__ void __launch_bounds__(512) dp_kernel() {
    __shared__ float edge[NW][32];
    int bx = blockIdx.x;
    int b = bx >> 1, dir = bx & 1;
    if (dir) dp_impl<true>(b, edge);
    else     dp_impl<false>(b, edge);
}

// ---------------------------------------------------------------------------
// Combine: logit2 = f2 + b2 - d2, de-diagonalize to row-major out,
// per-block max -> encoded atomicMax.
// ---------------------------------------------------------------------------
__global__ void __launch_bounds__(256) combine_kernel(float* __restrict__ out) {
    __shared__ float tile[32][257];
    __shared__ float smax[8];
    int b = blockIdx.y;
    int k0 = blockIdx.x * 32;
    const float* fd = g_f + (size_t)b * NDIAG * NN;
    const float* bd = g_b + (size_t)b * NDIAG * NN;
    const float* dd = g_ddiag + (size_t)b * NDIAG * NN;
    float* ob = out + (size_t)b * NN * NN;
    int tid = threadIdx.x, lane = tid & 31, w = tid >> 5;
    float vmax = -3.4e38f;

    for (int ih = 0; ih < 2; ih++) {
        int ibase = ih * 256;
        for (int kk = 0; kk < 32; kk++) {
            int k = k0 + kk;
            int i = ibase + tid;
            int j = k - i;
            float v = 0.0f;
            if (j >= 0 && j < NN) {
                int a = k * NN + i;
                v = fd[a] + bd[(1022 - k) * NN + (511 - i)] - dd[a];
                vmax = fmaxf(vmax, v);
            }
            tile[kk][tid] = v;
        }
        __syncthreads();
        for (int rr = 0; rr < 32; rr++) {
            int i = ibase + w * 32 + rr;
            int jlo = max(0, k0 - i);
            int jhi = min(NN - 1, k0 + 31 - i);
            int j = jlo + lane;
            if (j <= jhi) {
                int kk = i + j - k0;
                ob[(size_t)i * NN + j] = tile[kk][i - ibase];
            }
        }
        __syncthreads();
    }

#pragma unroll
    for (int o = 16; o > 0; o >>= 1)
        vmax = fmaxf(vmax, __shfl_xor_sync(0xffffffffu, vmax, o));
    if (lane == 0) smax[w] = vmax;
    __syncthreads();
    if (tid == 0) {
        float v = smax[0];
#pragma unroll
        for (int q = 1; q < 8; q++) v = fmaxf(v, smax[q]);
        atomicMax(&g_maxu, fenc(v));
    }
}

__global__ void __launch_bounds__(256) finish_kernel(float* __restrict__ out, int n4) {
    float mx = fdec(g_maxu);
    float4* o4 = (float4*)out;
    int idx = blockIdx.x * blockDim.x + threadIdx.x;
    int stride = gridDim.x * blockDim.x;
    for (int t = idx; t < n4; t += stride) {
        float4 v = o4[t];
        v.x = (v.x - mx) * LN2F;
        v.y = (v.y - mx) * LN2F;
        v.z = (v.z - mx) * LN2F;
        v.w = (v.w - mx) * LN2F;
        o4[t] = v;
    }
}

extern "C" void kernel_launch(void* const* d_in, const int* in_sizes, int n_in,
                              void* d_out, int out_size) {
    const float* d = (const float*)d_in[0];
    float* out = (float*)d_out;

    init_max_kernel<<<1, 1>>>();

    dim3 dgrid(16, 16, BATCH);
    diagize_kernel<<<dgrid, 256>>>(d);

    dp_kernel<<<BATCH * 2, 512>>>();

    dim3 cgrid(32, BATCH);
    combine_kernel<<<cgrid, 256>>>(out);

    finish_kernel<<<4096, 256>>>(out, out_size / 4);
}